// round 15
// baseline (speedup 1.0000x reference)
#include <cuda_runtime.h>
#include <cuda_bf16.h>
#include <cstdint>
#include <math.h>

#define T_STEPS 512
#define BATCH   64
#define DIN     256
#define HID     512
#define NGATE4  2048   // 4*H
#define KDH     768    // D+H
#define GSP2    36     // gate smem pitch (float2-aligned rows)

// -------- device scratch --------
__device__ float g_xg[(size_t)T_STEPS * BATCH * NGATE4];
__device__ unsigned int g_cnt[8];   // 8 counters, 8 CTAs each

// h state as bf16 hi/lo planes, ping-pong
__device__ __nv_bfloat16 g_hbhi[2][BATCH * HID];
__device__ __nv_bfloat16 g_hblo[2][BATCH * HID];

// bf16 split operands for tensor xgemm
__device__ __nv_bfloat16 g_xhi[(size_t)T_STEPS * BATCH * DIN];
__device__ __nv_bfloat16 g_xlo[(size_t)T_STEPS * BATCH * DIN];
__device__ __nv_bfloat16 g_whi[(size_t)NGATE4 * DIN];
__device__ __nv_bfloat16 g_wlo[(size_t)NGATE4 * DIN];
__device__ float g_ball[NGATE4];

__device__ __forceinline__ float fsigm(float x) {
    return __fdividef(1.0f, 1.0f + __expf(-x));
}
__device__ __forceinline__ float ftanh(float x) {
    float e = __expf(2.0f * x);
    return 1.0f - __fdividef(2.0f, e + 1.0f);
}

// -------- init --------
__global__ void init_kernel() {
    int idx = blockIdx.x * blockDim.x + threadIdx.x;
    if (idx < 8) g_cnt[idx] = 0u;
    int total = BATCH * HID;
    for (int i = idx; i < total; i += gridDim.x * blockDim.x) {
        g_hbhi[0][i] = __float2bfloat16(0.0f);
        g_hblo[0][i] = __float2bfloat16(0.0f);
    }
}

// -------- split --------
__global__ void split_kernel(
    const float* __restrict__ X,
    const float* __restrict__ Wf, const float* __restrict__ bf,
    const float* __restrict__ Wi, const float* __restrict__ bi,
    const float* __restrict__ Wg, const float* __restrict__ bg,
    const float* __restrict__ Wo, const float* __restrict__ bo)
{
    const int stride = gridDim.x * blockDim.x;
    int idx0 = blockIdx.x * blockDim.x + threadIdx.x;

    const size_t XN = (size_t)T_STEPS * BATCH * DIN;
    for (size_t i = idx0; i < XN; i += stride) {
        float x = X[i];
        __nv_bfloat16 h = __float2bfloat16(x);
        g_xhi[i] = h;
        g_xlo[i] = __float2bfloat16(x - __bfloat162float(h));
    }
    const size_t WN = (size_t)NGATE4 * DIN;
    for (size_t i = idx0; i < WN; i += stride) {
        int r = (int)(i >> 8);
        int k = (int)(i & 255);
        int g = r >> 9, u = r & 511;
        const float* Wp = (g == 0) ? Wf : (g == 1) ? Wi : (g == 2) ? Wg : Wo;
        float w = Wp[(size_t)u * KDH + k];
        __nv_bfloat16 h = __float2bfloat16(w);
        g_whi[i] = h;
        g_wlo[i] = __float2bfloat16(w - __bfloat162float(h));
    }
    for (int r = idx0; r < NGATE4; r += stride) {
        int g = r >> 9, u = r & 511;
        const float* bp = (g == 0) ? bf : (g == 1) ? bi : (g == 2) ? bg : bo;
        g_ball[r] = bp[u];
    }
}

// ---- helpers (base ISA) ----
__device__ __forceinline__ uint32_t smem_u32(const void* p) {
    uint32_t a;
    asm("{ .reg .u64 t; cvta.to.shared.u64 t, %1; cvt.u32.u64 %0, t; }"
        : "=r"(a) : "l"(p));
    return a;
}
__device__ __forceinline__ void ldmx4(uint32_t* r, uint32_t addr) {
    asm volatile("ldmatrix.sync.aligned.m8n8.x4.shared.b16 {%0,%1,%2,%3}, [%4];"
                 : "=r"(r[0]), "=r"(r[1]), "=r"(r[2]), "=r"(r[3]) : "r"(addr));
}
__device__ __forceinline__ void ldmx2(uint32_t* r, uint32_t addr) {
    asm volatile("ldmatrix.sync.aligned.m8n8.x2.shared.b16 {%0,%1}, [%2];"
                 : "=r"(r[0]), "=r"(r[1]) : "r"(addr));
}
__device__ __forceinline__ void mma_bf16(float* d, const uint32_t* a, const uint32_t* b) {
    asm volatile(
        "mma.sync.aligned.m16n8k16.row.col.f32.bf16.bf16.f32 "
        "{%0,%1,%2,%3}, {%4,%5,%6,%7}, {%8,%9}, {%0,%1,%2,%3};"
        : "+f"(d[0]), "+f"(d[1]), "+f"(d[2]), "+f"(d[3])
        : "r"(a[0]), "r"(a[1]), "r"(a[2]), "r"(a[3]), "r"(b[0]), "r"(b[1]));
}
__device__ __forceinline__ void cp16(uint32_t dst, const void* src) {
    asm volatile("cp.async.cg.shared.global [%0], [%1], 16;"
                 :: "r"(dst), "l"(src) : "memory");
}
__device__ __forceinline__ void cp_commit() {
    asm volatile("cp.async.commit_group;" ::: "memory");
}
__device__ __forceinline__ unsigned ld_acq(const unsigned* p) {
    unsigned v;
    asm volatile("ld.acquire.gpu.global.u32 %0, [%1];" : "=r"(v) : "l"(p) : "memory");
    return v;
}

// ======================= xgemm (validated) =======================
#define SM_AHI 0
#define SM_ALO 16384
#define SM_BHI 32768
#define SM_BLO 49152
#define SM_MMA_TOTAL 65536

__global__ __launch_bounds__(256) void xgemm_mma_kernel()
{
    extern __shared__ char smem[];
    const uint32_t sb = smem_u32(smem);
    const int tid  = threadIdx.x;
    const int lane = tid & 31;
    const int wid  = tid >> 5;
    const int wm   = wid & 1;
    const int wn   = wid >> 1;
    const int mBase = blockIdx.y * 128;
    const int nBase = blockIdx.x * 128;

    float acc[4][4][4];
#pragma unroll
    for (int i = 0; i < 4; ++i)
#pragma unroll
        for (int j = 0; j < 4; ++j)
#pragma unroll
            for (int q = 0; q < 4; ++q) acc[i][j][q] = 0.0f;

    const int lrow = lane & 7;
    const int lsel = lane >> 3;
    const int a_r_off = ((lsel & 1) << 3) + lrow;
    const int a_k_off = (lsel & 2) << 2;
    const int b_k_off = (lane & 8);

    const int ldRow = tid >> 1;
    const int ldQ   = (tid & 1) * 4;

    for (int c = 0; c < 4; ++c) {
        const uint4* pahi = (const uint4*)(g_xhi + (size_t)(mBase + ldRow) * DIN + c * 64);
        const uint4* palo = (const uint4*)(g_xlo + (size_t)(mBase + ldRow) * DIN + c * 64);
        const uint4* pbhi = (const uint4*)(g_whi + (size_t)(nBase + ldRow) * DIN + c * 64);
        const uint4* pblo = (const uint4*)(g_wlo + (size_t)(nBase + ldRow) * DIN + c * 64);
        if (c > 0) __syncthreads();
#pragma unroll
        for (int i = 0; i < 4; ++i) {
            uint32_t off = ldRow * 128 + (ldQ + i) * 16;
            uint32_t sw  = off ^ ((off >> 3) & 0x70);
            *(uint4*)(smem + SM_AHI + sw) = pahi[ldQ + i];
            *(uint4*)(smem + SM_ALO + sw) = palo[ldQ + i];
            *(uint4*)(smem + SM_BHI + sw) = pbhi[ldQ + i];
            *(uint4*)(smem + SM_BLO + sw) = pblo[ldQ + i];
        }
        __syncthreads();

#pragma unroll
        for (int pass = 0; pass < 3; ++pass) {
            const uint32_t abase = sb + ((pass < 2) ? SM_AHI : SM_ALO);
            const uint32_t bbase = sb + ((pass == 1) ? SM_BLO : SM_BHI);
#pragma unroll
            for (int k16 = 0; k16 < 4; ++k16) {
                uint32_t afr[4][4];
#pragma unroll
                for (int mf = 0; mf < 4; ++mf) {
                    int r  = wm * 64 + mf * 16 + a_r_off;
                    int kk = k16 * 16 + a_k_off;
                    uint32_t off = r * 128 + kk * 2;
                    off ^= (off >> 3) & 0x70;
                    ldmx4(afr[mf], abase + off);
                }
                uint32_t bfr[4][2];
#pragma unroll
                for (int nf = 0; nf < 4; ++nf) {
                    int r  = wn * 32 + nf * 8 + lrow;
                    int kk = k16 * 16 + b_k_off;
                    uint32_t off = r * 128 + kk * 2;
                    off ^= (off >> 3) & 0x70;
                    ldmx2(bfr[nf], bbase + off);
                }
#pragma unroll
                for (int mf = 0; mf < 4; ++mf)
#pragma unroll
                    for (int nf = 0; nf < 4; ++nf)
                        mma_bf16(acc[mf][nf], afr[mf], bfr[nf]);
            }
        }
    }

#pragma unroll
    for (int nf = 0; nf < 4; ++nf) {
        int n = nBase + wn * 32 + nf * 8 + (lane & 3) * 2;
        float b0 = g_ball[n], b1 = g_ball[n + 1];
#pragma unroll
        for (int mf = 0; mf < 4; ++mf) {
            int r0 = mBase + wm * 64 + mf * 16 + (lane >> 2);
            float2 v0 = make_float2(acc[mf][nf][0] + b0, acc[mf][nf][1] + b1);
            float2 v1 = make_float2(acc[mf][nf][2] + b0, acc[mf][nf][3] + b1);
            *(float2*)&g_xg[(size_t)r0 * NGATE4 + n]       = v0;
            *(float2*)&g_xg[(size_t)(r0 + 8) * NGATE4 + n] = v1;
        }
    }
}

// ===== recurrent kernel: 64 CTAs x 8 units, HMMA, half-pipelined staging ====
#define HS_HI 0
#define HS_LO 65536
#define WS_HI 131072
#define WS_LO 163840
#define GS_OFF 196608
#define SM_REC_TOTAL (GS_OFF + 64 * GSP2 * 4)

__global__ __launch_bounds__(256, 1) void lstm_rec_mma_kernel(
    const float* __restrict__ Wf, const float* __restrict__ Wi,
    const float* __restrict__ Wg, const float* __restrict__ Wo,
    float* __restrict__ out)
{
    extern __shared__ char sm[];
    const uint32_t sb = smem_u32(sm);
    float* gs = (float*)(sm + GS_OFF);

    const int tid  = threadIdx.x;
    const int lane = tid & 31;
    const int wid  = tid >> 5;
    const int wm   = wid & 1;      // 2 warps over batch (32 rows each)
    const int wn   = wid >> 1;     // 4 warps over gate rows (8 each)
    const int cb   = blockIdx.x;
    const int u0   = cb * 8;       // 8 hidden units per CTA
    const int my_grp = cb >> 3;    // 8 groups of 8 CTAs

    // --- prologue: load + split W recurrent slice (32 rows x 512) ---
    for (int it = 0; it < 64; ++it) {
        int idx = it * 256 + tid;          // 0..16383
        int r = idx >> 9;                  // 0..31 (= g*8 + j)
        int k = idx & 511;
        int g = r >> 3, j = r & 7;
        const float* Wp = (g == 0) ? Wf : (g == 1) ? Wi : (g == 2) ? Wg : Wo;
        float w = Wp[(size_t)(u0 + j) * KDH + DIN + k];
        __nv_bfloat16 whi = __float2bfloat16(w);
        __nv_bfloat16 wlo = __float2bfloat16(w - __bfloat162float(whi));
        uint32_t off = r * 128 + (k & 63) * 2;
        off ^= (off >> 3) & 0x70;
        off += (k >> 6) * 4096;            // 32 rows x 128B per K-chunk
        *(__nv_bfloat16*)(sm + WS_HI + off) = whi;
        *(__nv_bfloat16*)(sm + WS_LO + off) = wlo;
    }
    __syncthreads();

    // --- preload B fragments (constant over all steps): n=8 per warp ---
    const int lrow = lane & 7;
    const int lsel = lane >> 3;
    uint32_t bhi[32][2], blo[32][2];
#pragma unroll
    for (int kk = 0; kk < 32; ++kk) {
        uint32_t off = (wn * 8 + lrow) * 128 + ((kk & 3) * 16 + (lane & 8)) * 2;
        off ^= (off >> 3) & 0x70;
        uint32_t base = (kk >> 2) * 4096 + off;
        ldmx2(bhi[kk], sb + WS_HI + base);
        ldmx2(blo[kk], sb + WS_LO + base);
    }

    const int a_r0 = wm * 32 + ((lsel & 1) << 3) + lrow;   // + m'*16
    const int a_k  = (lsel & 2) << 2;
    const int eb = tid >> 2;
    const int ej = tid & 3;

    // --- staging offsets: 16 iters; i<8 = K-chunks 0..3, i>=8 = chunks 4..7 --
    uint32_t soff[16];
    uint32_t goff[16];
#pragma unroll
    for (int i = 0; i < 16; ++i) {
        int ha = i >> 3;                 // half
        int j  = (i & 7) * 256 + tid;    // 0..2047 within half
        int row = j >> 5;                // 0..63
        int uu  = (j & 31) + ha * 32;    // 16B unit within row
        uint32_t off = row * 128 + (uu & 7) * 16;
        off ^= (off >> 3) & 0x70;
        soff[i] = (uu >> 3) * 8192 + off;
        goff[i] = row * HID + uu * 8;
    }

    float c_reg[2] = {0.f, 0.f};
    float h_last[2] = {0.f, 0.f};

    for (int t = 0; t < T_STEPS; ++t) {
        // prefetch xg for both owned units (independent of barrier)
        const float* xr0 = g_xg + (size_t)(t * BATCH + eb) * NGATE4 + u0 + ej;
        float xf0 = xr0[0 * HID], xi0 = xr0[1 * HID], xg0 = xr0[2 * HID], xo0 = xr0[3 * HID];
        float xf1 = xr0[0 * HID + 4], xi1 = xr0[1 * HID + 4], xg1 = xr0[2 * HID + 4], xo1 = xr0[3 * HID + 4];

        // ---- acquire ----
        if (t > 0) {
            if (tid < 8) {
                const unsigned target = 8u * (unsigned)t;
                while (ld_acq(&g_cnt[tid]) < target) { }
            }
            __syncthreads();
        }

        const __nv_bfloat16* hhi = g_hbhi[t & 1];
        const __nv_bfloat16* hlo = g_hblo[t & 1];

        // ---- issue both staging halves ----
#pragma unroll
        for (int i = 0; i < 8; ++i) {
            cp16(sb + HS_HI + soff[i], hhi + goff[i]);
            cp16(sb + HS_LO + soff[i], hlo + goff[i]);
        }
        cp_commit();
#pragma unroll
        for (int i = 8; i < 16; ++i) {
            cp16(sb + HS_HI + soff[i], hhi + goff[i]);
            cp16(sb + HS_LO + soff[i], hlo + goff[i]);
        }
        cp_commit();

        float c4[2][4] = {{0.f, 0.f, 0.f, 0.f}, {0.f, 0.f, 0.f, 0.f}};

        // ---- half 1: chunks 0..3 (overlaps half-2 staging) ----
        asm volatile("cp.async.wait_group 1;" ::: "memory");
        __syncthreads();
#pragma unroll
        for (int c = 0; c < 4; ++c) {
#pragma unroll
            for (int q = 0; q < 4; ++q) {
                const int kk = c * 4 + q;
#pragma unroll
                for (int mp = 0; mp < 2; ++mp) {
                    uint32_t off = (a_r0 + mp * 16) * 128 + (q * 16 + a_k) * 2;
                    off ^= (off >> 3) & 0x70;
                    uint32_t ahi4[4], alo4[4];
                    ldmx4(ahi4, sb + HS_HI + c * 8192 + off);
                    ldmx4(alo4, sb + HS_LO + c * 8192 + off);
                    mma_bf16(c4[mp], ahi4, bhi[kk]);
                    mma_bf16(c4[mp], ahi4, blo[kk]);
                    mma_bf16(c4[mp], alo4, bhi[kk]);
                }
            }
        }
        // ---- half 2: chunks 4..7 ----
        asm volatile("cp.async.wait_group 0;" ::: "memory");
        __syncthreads();
#pragma unroll
        for (int c = 4; c < 8; ++c) {
#pragma unroll
            for (int q = 0; q < 4; ++q) {
                const int kk = c * 4 + q;
#pragma unroll
                for (int mp = 0; mp < 2; ++mp) {
                    uint32_t off = (a_r0 + mp * 16) * 128 + (q * 16 + a_k) * 2;
                    off ^= (off >> 3) & 0x70;
                    uint32_t ahi4[4], alo4[4];
                    ldmx4(ahi4, sb + HS_HI + c * 8192 + off);
                    ldmx4(alo4, sb + HS_LO + c * 8192 + off);
                    mma_bf16(c4[mp], ahi4, bhi[kk]);
                    mma_bf16(c4[mp], ahi4, blo[kk]);
                    mma_bf16(c4[mp], alo4, bhi[kk]);
                }
            }
        }

        // ---- epilogue: fragments -> gs [64 batch][32 gate rows] ----
#pragma unroll
        for (int mp = 0; mp < 2; ++mp) {
            int row = wm * 32 + mp * 16 + (lane >> 2);
            int col = wn * 8 + (lane & 3) * 2;
            *(float2*)&gs[row * GSP2 + col]       = make_float2(c4[mp][0], c4[mp][1]);
            *(float2*)&gs[(row + 8) * GSP2 + col] = make_float2(c4[mp][2], c4[mp][3]);
        }
        __syncthreads();

        // ---- elementwise LSTM cell: 2 units per thread (j = ej, ej+4) ----
        float hv2[2];
#pragma unroll
        for (int s = 0; s < 2; ++s) {
            int j = ej + s * 4;
            float pf = gs[eb * GSP2 + 0  + j] + (s ? xf1 : xf0);
            float pi = gs[eb * GSP2 + 8  + j] + (s ? xi1 : xi0);
            float pg = gs[eb * GSP2 + 16 + j] + (s ? xg1 : xg0);
            float po = gs[eb * GSP2 + 24 + j] + (s ? xo1 : xo0);
            float fg = fsigm(pf);
            float ig = fsigm(pi);
            float gg = ftanh(pg);
            float og = fsigm(po);
            c_reg[s] = fg * c_reg[s] + ig * gg;
            float hv = og * ftanh(c_reg[s]);
            h_last[s] = hv;
            hv2[s] = hv;

            __nv_bfloat16 hb = __float2bfloat16(hv);
            __nv_bfloat16 lb = __float2bfloat16(hv - __bfloat162float(hb));
            g_hbhi[(t + 1) & 1][eb * HID + u0 + j] = hb;
            g_hblo[(t + 1) & 1][eb * HID + u0 + j] = lb;
        }

        // ---- release ----
        __syncthreads();
        if (tid == 0) {
            __threadfence();
            atomicAdd(&g_cnt[my_grp], 1u);
        }

        out[(size_t)t * (BATCH * HID) + eb * HID + u0 + ej]     = hv2[0];
        out[(size_t)t * (BATCH * HID) + eb * HID + u0 + ej + 4] = hv2[1];
    }

    const size_t off = (size_t)T_STEPS * BATCH * HID;
    out[off + eb * HID + u0 + ej]                    = h_last[0];
    out[off + eb * HID + u0 + ej + 4]                = h_last[1];
    out[off + BATCH * HID + eb * HID + u0 + ej]      = c_reg[0];
    out[off + BATCH * HID + eb * HID + u0 + ej + 4]  = c_reg[1];
}

extern "C" void kernel_launch(void* const* d_in, const int* in_sizes, int n_in,
                              void* d_out, int out_size) {
    const float* X  = (const float*)d_in[0];
    const float* Wf = (const float*)d_in[1];
    const float* bf = (const float*)d_in[2];
    const float* Wi = (const float*)d_in[3];
    const float* bi = (const float*)d_in[4];
    const float* Wg = (const float*)d_in[5];
    const float* bg = (const float*)d_in[6];
    const float* Wo = (const float*)d_in[7];
    const float* bo = (const float*)d_in[8];
    float* out = (float*)d_out;

    cudaFuncSetAttribute(xgemm_mma_kernel,
                         cudaFuncAttributeMaxDynamicSharedMemorySize, SM_MMA_TOTAL);
    cudaFuncSetAttribute(lstm_rec_mma_kernel,
                         cudaFuncAttributeMaxDynamicSharedMemorySize, SM_REC_TOTAL);

    init_kernel<<<64, 256>>>();
    split_kernel<<<1024, 256>>>(X, Wf, bf, Wi, bi, Wg, bg, Wo, bo);
    xgemm_mma_kernel<<<dim3(16, 256), 256, SM_MMA_TOTAL>>>();
    lstm_rec_mma_kernel<<<64, 256, SM_REC_TOTAL>>>(Wf, Wi, Wg, Wo, out);
}

// round 16
// speedup vs baseline: 1.2209x; 1.2209x over previous
#include <cuda_runtime.h>
#include <cuda_bf16.h>
#include <cstdint>
#include <math.h>

#define T_STEPS 512
#define BATCH   64
#define DIN     256
#define HID     512
#define NGATE4  2048   // 4*H
#define KDH     768    // D+H
#define GSP     18     // gate smem pitch

// -------- device scratch --------
__device__ float g_xg[(size_t)T_STEPS * BATCH * NGATE4];
__device__ unsigned int g_cnt[8];   // 8-way split step counters (16 CTAs each)

// h state as bf16 hi/lo planes, ping-pong
__device__ __nv_bfloat16 g_hbhi[2][BATCH * HID];
__device__ __nv_bfloat16 g_hblo[2][BATCH * HID];

// bf16 split operands for tensor xgemm
__device__ __nv_bfloat16 g_xhi[(size_t)T_STEPS * BATCH * DIN];
__device__ __nv_bfloat16 g_xlo[(size_t)T_STEPS * BATCH * DIN];
__device__ __nv_bfloat16 g_whi[(size_t)NGATE4 * DIN];
__device__ __nv_bfloat16 g_wlo[(size_t)NGATE4 * DIN];
__device__ float g_ball[NGATE4];

__device__ __forceinline__ float fsigm(float x) {
    return __fdividef(1.0f, 1.0f + __expf(-x));
}
__device__ __forceinline__ float ftanh(float x) {
    float e = __expf(2.0f * x);
    return 1.0f - __fdividef(2.0f, e + 1.0f);
}

// -------- init --------
__global__ void init_kernel() {
    int idx = blockIdx.x * blockDim.x + threadIdx.x;
    if (idx < 8) g_cnt[idx] = 0u;
    int total = BATCH * HID;
    for (int i = idx; i < total; i += gridDim.x * blockDim.x) {
        g_hbhi[0][i] = __float2bfloat16(0.0f);
        g_hblo[0][i] = __float2bfloat16(0.0f);
    }
}

// -------- split --------
__global__ void split_kernel(
    const float* __restrict__ X,
    const float* __restrict__ Wf, const float* __restrict__ bf,
    const float* __restrict__ Wi, const float* __restrict__ bi,
    const float* __restrict__ Wg, const float* __restrict__ bg,
    const float* __restrict__ Wo, const float* __restrict__ bo)
{
    const int stride = gridDim.x * blockDim.x;
    int idx0 = blockIdx.x * blockDim.x + threadIdx.x;

    const size_t XN = (size_t)T_STEPS * BATCH * DIN;
    for (size_t i = idx0; i < XN; i += stride) {
        float x = X[i];
        __nv_bfloat16 h = __float2bfloat16(x);
        g_xhi[i] = h;
        g_xlo[i] = __float2bfloat16(x - __bfloat162float(h));
    }
    const size_t WN = (size_t)NGATE4 * DIN;
    for (size_t i = idx0; i < WN; i += stride) {
        int r = (int)(i >> 8);
        int k = (int)(i & 255);
        int g = r >> 9, u = r & 511;
        const float* Wp = (g == 0) ? Wf : (g == 1) ? Wi : (g == 2) ? Wg : Wo;
        float w = Wp[(size_t)u * KDH + k];
        __nv_bfloat16 h = __float2bfloat16(w);
        g_whi[i] = h;
        g_wlo[i] = __float2bfloat16(w - __bfloat162float(h));
    }
    for (int r = idx0; r < NGATE4; r += stride) {
        int g = r >> 9, u = r & 511;
        const float* bp = (g == 0) ? bf : (g == 1) ? bi : (g == 2) ? bg : bo;
        g_ball[r] = bp[u];
    }
}

// ---- helpers (base ISA) ----
__device__ __forceinline__ uint32_t smem_u32(const void* p) {
    uint32_t a;
    asm("{ .reg .u64 t; cvta.to.shared.u64 t, %1; cvt.u32.u64 %0, t; }"
        : "=r"(a) : "l"(p));
    return a;
}
__device__ __forceinline__ void ldmx4(uint32_t* r, uint32_t addr) {
    asm volatile("ldmatrix.sync.aligned.m8n8.x4.shared.b16 {%0,%1,%2,%3}, [%4];"
                 : "=r"(r[0]), "=r"(r[1]), "=r"(r[2]), "=r"(r[3]) : "r"(addr));
}
__device__ __forceinline__ void ldmx2(uint32_t* r, uint32_t addr) {
    asm volatile("ldmatrix.sync.aligned.m8n8.x2.shared.b16 {%0,%1}, [%2];"
                 : "=r"(r[0]), "=r"(r[1]) : "r"(addr));
}
__device__ __forceinline__ void mma_bf16(float* d, const uint32_t* a, const uint32_t* b) {
    asm volatile(
        "mma.sync.aligned.m16n8k16.row.col.f32.bf16.bf16.f32 "
        "{%0,%1,%2,%3}, {%4,%5,%6,%7}, {%8,%9}, {%0,%1,%2,%3};"
        : "+f"(d[0]), "+f"(d[1]), "+f"(d[2]), "+f"(d[3])
        : "r"(a[0]), "r"(a[1]), "r"(a[2]), "r"(a[3]), "r"(b[0]), "r"(b[1]));
}
__device__ __forceinline__ void cp16(uint32_t dst, const void* src) {
    asm volatile("cp.async.cg.shared.global [%0], [%1], 16;"
                 :: "r"(dst), "l"(src) : "memory");
}
__device__ __forceinline__ void cp_commit() {
    asm volatile("cp.async.commit_group;" ::: "memory");
}
__device__ __forceinline__ void cp_wait0() {
    asm volatile("cp.async.wait_group 0;" ::: "memory");
}
__device__ __forceinline__ unsigned ld_acq(const unsigned* p) {
    unsigned v;
    asm volatile("ld.acquire.gpu.global.u32 %0, [%1];" : "=r"(v) : "l"(p) : "memory");
    return v;
}

// ======================= xgemm (validated) =======================
#define SM_AHI 0
#define SM_ALO 16384
#define SM_BHI 32768
#define SM_BLO 49152
#define SM_MMA_TOTAL 65536

__global__ __launch_bounds__(256) void xgemm_mma_kernel()
{
    extern __shared__ char smem[];
    const uint32_t sb = smem_u32(smem);
    const int tid  = threadIdx.x;
    const int lane = tid & 31;
    const int wid  = tid >> 5;
    const int wm   = wid & 1;
    const int wn   = wid >> 1;
    const int mBase = blockIdx.y * 128;
    const int nBase = blockIdx.x * 128;

    float acc[4][4][4];
#pragma unroll
    for (int i = 0; i < 4; ++i)
#pragma unroll
        for (int j = 0; j < 4; ++j)
#pragma unroll
            for (int q = 0; q < 4; ++q) acc[i][j][q] = 0.0f;

    const int lrow = lane & 7;
    const int lsel = lane >> 3;
    const int a_r_off = ((lsel & 1) << 3) + lrow;
    const int a_k_off = (lsel & 2) << 2;
    const int b_k_off = (lane & 8);

    const int ldRow = tid >> 1;
    const int ldQ   = (tid & 1) * 4;

    for (int c = 0; c < 4; ++c) {
        const uint4* pahi = (const uint4*)(g_xhi + (size_t)(mBase + ldRow) * DIN + c * 64);
        const uint4* palo = (const uint4*)(g_xlo + (size_t)(mBase + ldRow) * DIN + c * 64);
        const uint4* pbhi = (const uint4*)(g_whi + (size_t)(nBase + ldRow) * DIN + c * 64);
        const uint4* pblo = (const uint4*)(g_wlo + (size_t)(nBase + ldRow) * DIN + c * 64);
        if (c > 0) __syncthreads();
#pragma unroll
        for (int i = 0; i < 4; ++i) {
            uint32_t off = ldRow * 128 + (ldQ + i) * 16;
            uint32_t sw  = off ^ ((off >> 3) & 0x70);
            *(uint4*)(smem + SM_AHI + sw) = pahi[ldQ + i];
            *(uint4*)(smem + SM_ALO + sw) = palo[ldQ + i];
            *(uint4*)(smem + SM_BHI + sw) = pbhi[ldQ + i];
            *(uint4*)(smem + SM_BLO + sw) = pblo[ldQ + i];
        }
        __syncthreads();

#pragma unroll
        for (int pass = 0; pass < 3; ++pass) {
            const uint32_t abase = sb + ((pass < 2) ? SM_AHI : SM_ALO);
            const uint32_t bbase = sb + ((pass == 1) ? SM_BLO : SM_BHI);
#pragma unroll
            for (int k16 = 0; k16 < 4; ++k16) {
                uint32_t afr[4][4];
#pragma unroll
                for (int mf = 0; mf < 4; ++mf) {
                    int r  = wm * 64 + mf * 16 + a_r_off;
                    int kk = k16 * 16 + a_k_off;
                    uint32_t off = r * 128 + kk * 2;
                    off ^= (off >> 3) & 0x70;
                    ldmx4(afr[mf], abase + off);
                }
                uint32_t bfr[4][2];
#pragma unroll
                for (int nf = 0; nf < 4; ++nf) {
                    int r  = wn * 32 + nf * 8 + lrow;
                    int kk = k16 * 16 + b_k_off;
                    uint32_t off = r * 128 + kk * 2;
                    off ^= (off >> 3) & 0x70;
                    ldmx2(bfr[nf], bbase + off);
                }
#pragma unroll
                for (int mf = 0; mf < 4; ++mf)
#pragma unroll
                    for (int nf = 0; nf < 4; ++nf)
                        mma_bf16(acc[mf][nf], afr[mf], bfr[nf]);
            }
        }
    }

#pragma unroll
    for (int nf = 0; nf < 4; ++nf) {
        int n = nBase + wn * 32 + nf * 8 + (lane & 3) * 2;
        float b0 = g_ball[n], b1 = g_ball[n + 1];
#pragma unroll
        for (int mf = 0; mf < 4; ++mf) {
            int r0 = mBase + wm * 64 + mf * 16 + (lane >> 2);
            float2 v0 = make_float2(acc[mf][nf][0] + b0, acc[mf][nf][1] + b1);
            float2 v1 = make_float2(acc[mf][nf][2] + b0, acc[mf][nf][3] + b1);
            *(float2*)&g_xg[(size_t)r0 * NGATE4 + n]       = v0;
            *(float2*)&g_xg[(size_t)(r0 + 8) * NGATE4 + n] = v1;
        }
    }
}

// ==== recurrent kernel: HMMA + 2-stage pipelined acquire/stage/mma ====
#define HS_HI 0
#define HS_LO 65536
#define WS_HI 131072
#define WS_LO 147456
#define GS_OFF 163840
#define SM_REC_TOTAL (GS_OFF + 64 * GSP * 4)

__global__ __launch_bounds__(256, 1) void lstm_rec_mma_kernel(
    const float* __restrict__ Wf, const float* __restrict__ Wi,
    const float* __restrict__ Wg, const float* __restrict__ Wo,
    float* __restrict__ out)
{
    extern __shared__ char sm[];
    const uint32_t sb = smem_u32(sm);
    float* gs = (float*)(sm + GS_OFF);

    const int tid  = threadIdx.x;
    const int lane = tid & 31;
    const int wid  = tid >> 5;
    const int wm   = wid & 3;
    const int wn   = wid >> 2;
    const int cb   = blockIdx.x;
    const int u0   = cb * 4;
    const int my_grp = cb >> 4;            // 8 groups of 16 CTAs
    const bool halfA = (tid & 32) == 0;    // stages K-chunks 0..3

    // --- prologue: load + split W recurrent slice into SW128 chunks ---
    for (int it = 0; it < 32; ++it) {
        int idx = it * 256 + tid;
        int r = idx >> 9;
        int k = idx & 511;
        int g = r >> 2, j = r & 3;
        const float* Wp = (g == 0) ? Wf : (g == 1) ? Wi : (g == 2) ? Wg : Wo;
        float w = Wp[(size_t)(u0 + j) * KDH + DIN + k];
        __nv_bfloat16 whi = __float2bfloat16(w);
        __nv_bfloat16 wlo = __float2bfloat16(w - __bfloat162float(whi));
        uint32_t off = r * 128 + (k & 63) * 2;
        off ^= (off >> 3) & 0x70;
        off += (k >> 6) * 2048;
        *(__nv_bfloat16*)(sm + WS_HI + off) = whi;
        *(__nv_bfloat16*)(sm + WS_LO + off) = wlo;
    }
    __syncthreads();

    // --- preload B fragments (constant over all steps) ---
    const int lrow = lane & 7;
    const int lsel = lane >> 3;
    uint32_t bhi[32][2], blo[32][2];
#pragma unroll
    for (int kk = 0; kk < 32; ++kk) {
        uint32_t off = (wn * 8 + lrow) * 128 + ((kk & 3) * 16 + (lane & 8)) * 2;
        off ^= (off >> 3) & 0x70;
        uint32_t base = (kk >> 2) * 2048 + off;
        ldmx2(bhi[kk], sb + WS_HI + base);
        ldmx2(blo[kk], sb + WS_LO + base);
    }

    const int a_r = wm * 16 + ((lsel & 1) << 3) + lrow;
    const int a_k = (lsel & 2) << 2;
    const int eb = tid >> 2;
    const int ej = tid & 3;

    // --- t-invariant staging offsets (each thread serves ONE K-chunk) ---
    uint32_t soff[16];
    uint32_t goff[16];
#pragma unroll
    for (int i = 0; i < 16; ++i) {
        int idx = i * 256 + tid;        // 0..4095
        int row = idx >> 6;             // 0..63
        int u   = idx & 63;             // 16B unit within row (fixed per thread)
        uint32_t off = row * 128 + (u & 7) * 16;
        off ^= (off >> 3) & 0x70;
        soff[i] = (u >> 3) * 8192 + off;
        goff[i] = row * HID + u * 8;
    }

    float c_reg = 0.0f;
    float h_last = 0.0f;

    for (int t = 0; t < T_STEPS; ++t) {
        // prefetch xg (independent of barrier)
        const float* xr = g_xg + (size_t)(t * BATCH + eb) * NGATE4 + u0 + ej;
        float xf = xr[0 * HID], xi = xr[1 * HID], xg2 = xr[2 * HID], xo = xr[3 * HID];

        const unsigned target = 16u * (unsigned)t;

        // ---- acquire half A: threads 0..3 poll counters 0..3 ----
        if (t > 0 && tid < 4) {
            while (ld_acq(&g_cnt[tid]) < target) { }
        }
        __syncthreads();

        const __nv_bfloat16* hhi = g_hbhi[t & 1];
        const __nv_bfloat16* hlo = g_hblo[t & 1];

        // ---- half-A threads stage chunks 0..3 and complete ----
        if (halfA) {
#pragma unroll
            for (int i = 0; i < 16; ++i) {
                cp16(sb + HS_HI + soff[i], hhi + goff[i]);
                cp16(sb + HS_LO + soff[i], hlo + goff[i]);
            }
            cp_commit();
        }
        // ---- half-B acquire in the shadow: threads 32..35 poll 4..7 ----
        if (t > 0 && tid >= 32 && tid < 36) {
            while (ld_acq(&g_cnt[tid - 28]) < target) { }
        }
        if (halfA) cp_wait0();
        __syncthreads();   // chunks 0..3 visible; counters 4..7 passed

        // ---- half-B threads stage chunks 4..7 (overlaps mma below) ----
        if (!halfA) {
#pragma unroll
            for (int i = 0; i < 16; ++i) {
                cp16(sb + HS_HI + soff[i], hhi + goff[i]);
                cp16(sb + HS_LO + soff[i], hlo + goff[i]);
            }
            cp_commit();
        }

        // ---- mma chunks 0..3 ----
        float c4[4] = {0.f, 0.f, 0.f, 0.f};
#pragma unroll
        for (int c = 0; c < 4; ++c) {
#pragma unroll
            for (int q = 0; q < 4; ++q) {
                const int kk = c * 4 + q;
                uint32_t off = a_r * 128 + (q * 16 + a_k) * 2;
                off ^= (off >> 3) & 0x70;
                uint32_t ahi4[4], alo4[4];
                ldmx4(ahi4, sb + HS_HI + c * 8192 + off);
                ldmx4(alo4, sb + HS_LO + c * 8192 + off);
                mma_bf16(c4, ahi4, bhi[kk]);
                mma_bf16(c4, ahi4, blo[kk]);
                mma_bf16(c4, alo4, bhi[kk]);
            }
        }

        if (!halfA) cp_wait0();
        __syncthreads();   // chunks 4..7 visible

        // ---- mma chunks 4..7 ----
#pragma unroll
        for (int c = 4; c < 8; ++c) {
#pragma unroll
            for (int q = 0; q < 4; ++q) {
                const int kk = c * 4 + q;
                uint32_t off = a_r * 128 + (q * 16 + a_k) * 2;
                off ^= (off >> 3) & 0x70;
                uint32_t ahi4[4], alo4[4];
                ldmx4(ahi4, sb + HS_HI + c * 8192 + off);
                ldmx4(alo4, sb + HS_LO + c * 8192 + off);
                mma_bf16(c4, ahi4, bhi[kk]);
                mma_bf16(c4, ahi4, blo[kk]);
                mma_bf16(c4, alo4, bhi[kk]);
            }
        }

        // ---- epilogue: fragments -> gs ----
        {
            int row = wm * 16 + (lane >> 2);
            int col = wn * 8 + (lane & 3) * 2;
            *(float2*)&gs[row * GSP + col]       = make_float2(c4[0], c4[1]);
            *(float2*)&gs[(row + 8) * GSP + col] = make_float2(c4[2], c4[3]);
        }
        __syncthreads();

        // ---- elementwise LSTM cell ----
        float pf = gs[eb * GSP + 0  + ej] + xf;
        float pi = gs[eb * GSP + 4  + ej] + xi;
        float pg = gs[eb * GSP + 8  + ej] + xg2;
        float po = gs[eb * GSP + 12 + ej] + xo;
        float fg = fsigm(pf);
        float ig = fsigm(pi);
        float gg = ftanh(pg);
        float og = fsigm(po);
        c_reg = fg * c_reg + ig * gg;
        float hv = og * ftanh(c_reg);
        h_last = hv;

        __nv_bfloat16 hb = __float2bfloat16(hv);
        __nv_bfloat16 lb = __float2bfloat16(hv - __bfloat162float(hb));
        g_hbhi[(t + 1) & 1][eb * HID + u0 + ej] = hb;
        g_hblo[(t + 1) & 1][eb * HID + u0 + ej] = lb;

        // ---- release ----
        __syncthreads();
        if (tid == 0) {
            __threadfence();
            atomicAdd(&g_cnt[my_grp], 1u);
        }

        out[(size_t)t * (BATCH * HID) + eb * HID + u0 + ej] = hv;
    }

    const size_t off = (size_t)T_STEPS * BATCH * HID;
    out[off + eb * HID + u0 + ej]               = h_last;
    out[off + BATCH * HID + eb * HID + u0 + ej] = c_reg;
}

extern "C" void kernel_launch(void* const* d_in, const int* in_sizes, int n_in,
                              void* d_out, int out_size) {
    const float* X  = (const float*)d_in[0];
    const float* Wf = (const float*)d_in[1];
    const float* bf = (const float*)d_in[2];
    const float* Wi = (const float*)d_in[3];
    const float* bi = (const float*)d_in[4];
    const float* Wg = (const float*)d_in[5];
    const float* bg = (const float*)d_in[6];
    const float* Wo = (const float*)d_in[7];
    const float* bo = (const float*)d_in[8];
    float* out = (float*)d_out;

    cudaFuncSetAttribute(xgemm_mma_kernel,
                         cudaFuncAttributeMaxDynamicSharedMemorySize, SM_MMA_TOTAL);
    cudaFuncSetAttribute(lstm_rec_mma_kernel,
                         cudaFuncAttributeMaxDynamicSharedMemorySize, SM_REC_TOTAL);

    init_kernel<<<64, 256>>>();
    split_kernel<<<1024, 256>>>(X, Wf, bf, Wi, bi, Wg, bg, Wo, bo);
    xgemm_mma_kernel<<<dim3(16, 256), 256, SM_MMA_TOTAL>>>();
    lstm_rec_mma_kernel<<<128, 256, SM_REC_TOTAL>>>(Wf, Wi, Wg, Wo, out);
}

// round 17
// speedup vs baseline: 1.2584x; 1.0307x over previous
#include <cuda_runtime.h>
#include <cuda_bf16.h>
#include <cstdint>
#include <math.h>

#define T_STEPS 512
#define BATCH   64
#define DIN     256
#define HID     512
#define NGATE4  2048   // 4*H
#define KDH     768    // D+H
#define GSP     18     // gate smem pitch

// -------- device scratch --------
__device__ float g_xg[(size_t)T_STEPS * BATCH * NGATE4];
__device__ unsigned int g_cnt[8];   // 8-way split step counters (16 CTAs each)

// h state as bf16 hi/lo planes, ping-pong
__device__ __nv_bfloat16 g_hbhi[2][BATCH * HID];
__device__ __nv_bfloat16 g_hblo[2][BATCH * HID];

// bf16 split operands for tensor xgemm
__device__ __nv_bfloat16 g_xhi[(size_t)T_STEPS * BATCH * DIN];
__device__ __nv_bfloat16 g_xlo[(size_t)T_STEPS * BATCH * DIN];
__device__ __nv_bfloat16 g_whi[(size_t)NGATE4 * DIN];
__device__ __nv_bfloat16 g_wlo[(size_t)NGATE4 * DIN];
__device__ float g_ball[NGATE4];

__device__ __forceinline__ float fsigm(float x) {
    return __fdividef(1.0f, 1.0f + __expf(-x));
}
__device__ __forceinline__ float ftanh(float x) {
    float e = __expf(2.0f * x);
    return 1.0f - __fdividef(2.0f, e + 1.0f);
}

// -------- init --------
__global__ void init_kernel() {
    int idx = blockIdx.x * blockDim.x + threadIdx.x;
    if (idx < 8) g_cnt[idx] = 0u;
    int total = BATCH * HID;
    for (int i = idx; i < total; i += gridDim.x * blockDim.x) {
        g_hbhi[0][i] = __float2bfloat16(0.0f);
        g_hblo[0][i] = __float2bfloat16(0.0f);
    }
}

// -------- split --------
__global__ void split_kernel(
    const float* __restrict__ X,
    const float* __restrict__ Wf, const float* __restrict__ bf,
    const float* __restrict__ Wi, const float* __restrict__ bi,
    const float* __restrict__ Wg, const float* __restrict__ bg,
    const float* __restrict__ Wo, const float* __restrict__ bo)
{
    const int stride = gridDim.x * blockDim.x;
    int idx0 = blockIdx.x * blockDim.x + threadIdx.x;

    const size_t XN = (size_t)T_STEPS * BATCH * DIN;
    for (size_t i = idx0; i < XN; i += stride) {
        float x = X[i];
        __nv_bfloat16 h = __float2bfloat16(x);
        g_xhi[i] = h;
        g_xlo[i] = __float2bfloat16(x - __bfloat162float(h));
    }
    const size_t WN = (size_t)NGATE4 * DIN;
    for (size_t i = idx0; i < WN; i += stride) {
        int r = (int)(i >> 8);
        int k = (int)(i & 255);
        int g = r >> 9, u = r & 511;
        const float* Wp = (g == 0) ? Wf : (g == 1) ? Wi : (g == 2) ? Wg : Wo;
        float w = Wp[(size_t)u * KDH + k];
        __nv_bfloat16 h = __float2bfloat16(w);
        g_whi[i] = h;
        g_wlo[i] = __float2bfloat16(w - __bfloat162float(h));
    }
    for (int r = idx0; r < NGATE4; r += stride) {
        int g = r >> 9, u = r & 511;
        const float* bp = (g == 0) ? bf : (g == 1) ? bi : (g == 2) ? bg : bo;
        g_ball[r] = bp[u];
    }
}

// ---- helpers (base ISA) ----
__device__ __forceinline__ uint32_t smem_u32(const void* p) {
    uint32_t a;
    asm("{ .reg .u64 t; cvta.to.shared.u64 t, %1; cvt.u32.u64 %0, t; }"
        : "=r"(a) : "l"(p));
    return a;
}
__device__ __forceinline__ void ldmx4(uint32_t* r, uint32_t addr) {
    asm volatile("ldmatrix.sync.aligned.m8n8.x4.shared.b16 {%0,%1,%2,%3}, [%4];"
                 : "=r"(r[0]), "=r"(r[1]), "=r"(r[2]), "=r"(r[3]) : "r"(addr));
}
__device__ __forceinline__ void ldmx2(uint32_t* r, uint32_t addr) {
    asm volatile("ldmatrix.sync.aligned.m8n8.x2.shared.b16 {%0,%1}, [%2];"
                 : "=r"(r[0]), "=r"(r[1]) : "r"(addr));
}
__device__ __forceinline__ void mma_bf16(float* d, const uint32_t* a, const uint32_t* b) {
    asm volatile(
        "mma.sync.aligned.m16n8k16.row.col.f32.bf16.bf16.f32 "
        "{%0,%1,%2,%3}, {%4,%5,%6,%7}, {%8,%9}, {%0,%1,%2,%3};"
        : "+f"(d[0]), "+f"(d[1]), "+f"(d[2]), "+f"(d[3])
        : "r"(a[0]), "r"(a[1]), "r"(a[2]), "r"(a[3]), "r"(b[0]), "r"(b[1]));
}
__device__ __forceinline__ void cp16(uint32_t dst, const void* src) {
    asm volatile("cp.async.cg.shared.global [%0], [%1], 16;"
                 :: "r"(dst), "l"(src) : "memory");
}
__device__ __forceinline__ void cp_wait_all() {
    asm volatile("cp.async.commit_group;\n\tcp.async.wait_group 0;" ::: "memory");
}
__device__ __forceinline__ unsigned ld_acq(const unsigned* p) {
    unsigned v;
    asm volatile("ld.acquire.gpu.global.u32 %0, [%1];" : "=r"(v) : "l"(p) : "memory");
    return v;
}

// ======================= xgemm (validated) =======================
#define SM_AHI 0
#define SM_ALO 16384
#define SM_BHI 32768
#define SM_BLO 49152
#define SM_MMA_TOTAL 65536

__global__ __launch_bounds__(256) void xgemm_mma_kernel()
{
    extern __shared__ char smem[];
    const uint32_t sb = smem_u32(smem);
    const int tid  = threadIdx.x;
    const int lane = tid & 31;
    const int wid  = tid >> 5;
    const int wm   = wid & 1;
    const int wn   = wid >> 1;
    const int mBase = blockIdx.y * 128;
    const int nBase = blockIdx.x * 128;

    float acc[4][4][4];
#pragma unroll
    for (int i = 0; i < 4; ++i)
#pragma unroll
        for (int j = 0; j < 4; ++j)
#pragma unroll
            for (int q = 0; q < 4; ++q) acc[i][j][q] = 0.0f;

    const int lrow = lane & 7;
    const int lsel = lane >> 3;
    const int a_r_off = ((lsel & 1) << 3) + lrow;
    const int a_k_off = (lsel & 2) << 2;
    const int b_k_off = (lane & 8);

    const int ldRow = tid >> 1;
    const int ldQ   = (tid & 1) * 4;

    for (int c = 0; c < 4; ++c) {
        const uint4* pahi = (const uint4*)(g_xhi + (size_t)(mBase + ldRow) * DIN + c * 64);
        const uint4* palo = (const uint4*)(g_xlo + (size_t)(mBase + ldRow) * DIN + c * 64);
        const uint4* pbhi = (const uint4*)(g_whi + (size_t)(nBase + ldRow) * DIN + c * 64);
        const uint4* pblo = (const uint4*)(g_wlo + (size_t)(nBase + ldRow) * DIN + c * 64);
        if (c > 0) __syncthreads();
#pragma unroll
        for (int i = 0; i < 4; ++i) {
            uint32_t off = ldRow * 128 + (ldQ + i) * 16;
            uint32_t sw  = off ^ ((off >> 3) & 0x70);
            *(uint4*)(smem + SM_AHI + sw) = pahi[ldQ + i];
            *(uint4*)(smem + SM_ALO + sw) = palo[ldQ + i];
            *(uint4*)(smem + SM_BHI + sw) = pbhi[ldQ + i];
            *(uint4*)(smem + SM_BLO + sw) = pblo[ldQ + i];
        }
        __syncthreads();

#pragma unroll
        for (int pass = 0; pass < 3; ++pass) {
            const uint32_t abase = sb + ((pass < 2) ? SM_AHI : SM_ALO);
            const uint32_t bbase = sb + ((pass == 1) ? SM_BLO : SM_BHI);
#pragma unroll
            for (int k16 = 0; k16 < 4; ++k16) {
                uint32_t afr[4][4];
#pragma unroll
                for (int mf = 0; mf < 4; ++mf) {
                    int r  = wm * 64 + mf * 16 + a_r_off;
                    int kk = k16 * 16 + a_k_off;
                    uint32_t off = r * 128 + kk * 2;
                    off ^= (off >> 3) & 0x70;
                    ldmx4(afr[mf], abase + off);
                }
                uint32_t bfr[4][2];
#pragma unroll
                for (int nf = 0; nf < 4; ++nf) {
                    int r  = wn * 32 + nf * 8 + lrow;
                    int kk = k16 * 16 + b_k_off;
                    uint32_t off = r * 128 + kk * 2;
                    off ^= (off >> 3) & 0x70;
                    ldmx2(bfr[nf], bbase + off);
                }
#pragma unroll
                for (int mf = 0; mf < 4; ++mf)
#pragma unroll
                    for (int nf = 0; nf < 4; ++nf)
                        mma_bf16(acc[mf][nf], afr[mf], bfr[nf]);
            }
        }
    }

#pragma unroll
    for (int nf = 0; nf < 4; ++nf) {
        int n = nBase + wn * 32 + nf * 8 + (lane & 3) * 2;
        float b0 = g_ball[n], b1 = g_ball[n + 1];
#pragma unroll
        for (int mf = 0; mf < 4; ++mf) {
            int r0 = mBase + wm * 64 + mf * 16 + (lane >> 2);
            float2 v0 = make_float2(acc[mf][nf][0] + b0, acc[mf][nf][1] + b1);
            float2 v1 = make_float2(acc[mf][nf][2] + b0, acc[mf][nf][3] + b1);
            *(float2*)&g_xg[(size_t)r0 * NGATE4 + n]       = v0;
            *(float2*)&g_xg[(size_t)(r0 + 8) * NGATE4 + n] = v1;
        }
    }
}

// ===== recurrent kernel: R14 structure + 3-way split accumulators =====
#define HS_HI 0
#define HS_LO 65536
#define WS_HI 131072
#define WS_LO 147456
#define GS_OFF 163840
#define SM_REC_TOTAL (GS_OFF + 64 * GSP * 4)

__global__ __launch_bounds__(256, 1) void lstm_rec_mma_kernel(
    const float* __restrict__ Wf, const float* __restrict__ Wi,
    const float* __restrict__ Wg, const float* __restrict__ Wo,
    float* __restrict__ out)
{
    extern __shared__ char sm[];
    const uint32_t sb = smem_u32(sm);
    float* gs = (float*)(sm + GS_OFF);

    const int tid  = threadIdx.x;
    const int lane = tid & 31;
    const int wid  = tid >> 5;
    const int wm   = wid & 3;
    const int wn   = wid >> 2;
    const int cb   = blockIdx.x;
    const int u0   = cb * 4;
    const int my_grp = cb >> 4;

    // --- prologue: load + split W recurrent slice into SW128 chunks ---
    for (int it = 0; it < 32; ++it) {
        int idx = it * 256 + tid;
        int r = idx >> 9;
        int k = idx & 511;
        int g = r >> 2, j = r & 3;
        const float* Wp = (g == 0) ? Wf : (g == 1) ? Wi : (g == 2) ? Wg : Wo;
        float w = Wp[(size_t)(u0 + j) * KDH + DIN + k];
        __nv_bfloat16 whi = __float2bfloat16(w);
        __nv_bfloat16 wlo = __float2bfloat16(w - __bfloat162float(whi));
        uint32_t off = r * 128 + (k & 63) * 2;
        off ^= (off >> 3) & 0x70;
        off += (k >> 6) * 2048;
        *(__nv_bfloat16*)(sm + WS_HI + off) = whi;
        *(__nv_bfloat16*)(sm + WS_LO + off) = wlo;
    }
    __syncthreads();

    // --- preload B fragments (constant over all steps) ---
    const int lrow = lane & 7;
    const int lsel = lane >> 3;
    uint32_t bhi[32][2], blo[32][2];
#pragma unroll
    for (int kk = 0; kk < 32; ++kk) {
        uint32_t off = (wn * 8 + lrow) * 128 + ((kk & 3) * 16 + (lane & 8)) * 2;
        off ^= (off >> 3) & 0x70;
        uint32_t base = (kk >> 2) * 2048 + off;
        ldmx2(bhi[kk], sb + WS_HI + base);
        ldmx2(blo[kk], sb + WS_LO + base);
    }

    const int a_r = wm * 16 + ((lsel & 1) << 3) + lrow;
    const int a_k = (lsel & 2) << 2;
    const int eb = tid >> 2;
    const int ej = tid & 3;

    // --- t-invariant staging offsets: 16 x 16B units of one h plane ---
    uint32_t soff[16];
    uint32_t goff[16];
#pragma unroll
    for (int i = 0; i < 16; ++i) {
        int idx = i * 256 + tid;
        int row = idx >> 6;
        int u   = idx & 63;
        uint32_t off = row * 128 + (u & 7) * 16;
        off ^= (off >> 3) & 0x70;
        soff[i] = (u >> 3) * 8192 + off;
        goff[i] = row * HID + u * 8;
    }

    float c_reg = 0.0f;
    float h_last = 0.0f;

    for (int t = 0; t < T_STEPS; ++t) {
        // prefetch xg (independent of barrier)
        const float* xr = g_xg + (size_t)(t * BATCH + eb) * NGATE4 + u0 + ej;
        float xf = xr[0 * HID], xi = xr[1 * HID], xg2 = xr[2 * HID], xo = xr[3 * HID];

        // ---- acquire: threads 0..7 each poll one split counter ----
        if (t > 0) {
            if (tid < 8) {
                const unsigned target = 16u * (unsigned)t;
                while (ld_acq(&g_cnt[tid]) < target) { }
            }
            __syncthreads();
        }

        const __nv_bfloat16* hhi = g_hbhi[t & 1];
        const __nv_bfloat16* hlo = g_hblo[t & 1];

        // ---- stage full h (both planes) via cp.async, ONE sync ----
#pragma unroll
        for (int i = 0; i < 16; ++i) {
            cp16(sb + HS_HI + soff[i], hhi + goff[i]);
            cp16(sb + HS_LO + soff[i], hlo + goff[i]);
        }
        cp_wait_all();
        __syncthreads();

        // ---- mma chain: 3 independent accumulator chains ----
        float c4a[4] = {0.f, 0.f, 0.f, 0.f};   // ahi * bhi
        float c4b[4] = {0.f, 0.f, 0.f, 0.f};   // ahi * blo
        float c4c[4] = {0.f, 0.f, 0.f, 0.f};   // alo * bhi
#pragma unroll
        for (int c = 0; c < 8; ++c) {
#pragma unroll
            for (int q = 0; q < 4; ++q) {
                const int kk = c * 4 + q;
                uint32_t off = a_r * 128 + (q * 16 + a_k) * 2;
                off ^= (off >> 3) & 0x70;
                uint32_t ahi4[4], alo4[4];
                ldmx4(ahi4, sb + HS_HI + c * 8192 + off);
                ldmx4(alo4, sb + HS_LO + c * 8192 + off);
                mma_bf16(c4a, ahi4, bhi[kk]);
                mma_bf16(c4b, ahi4, blo[kk]);
                mma_bf16(c4c, alo4, bhi[kk]);
            }
        }
        float c4[4];
#pragma unroll
        for (int q = 0; q < 4; ++q) c4[q] = c4a[q] + c4b[q] + c4c[q];

        // ---- epilogue: fragments -> gs ----
        {
            int row = wm * 16 + (lane >> 2);
            int col = wn * 8 + (lane & 3) * 2;
            *(float2*)&gs[row * GSP + col]       = make_float2(c4[0], c4[1]);
            *(float2*)&gs[(row + 8) * GSP + col] = make_float2(c4[2], c4[3]);
        }
        __syncthreads();

        // ---- elementwise LSTM cell ----
        float pf = gs[eb * GSP + 0  + ej] + xf;
        float pi = gs[eb * GSP + 4  + ej] + xi;
        float pg = gs[eb * GSP + 8  + ej] + xg2;
        float po = gs[eb * GSP + 12 + ej] + xo;
        float fg = fsigm(pf);
        float ig = fsigm(pi);
        float gg = ftanh(pg);
        float og = fsigm(po);
        c_reg = fg * c_reg + ig * gg;
        float hv = og * ftanh(c_reg);
        h_last = hv;

        __nv_bfloat16 hb = __float2bfloat16(hv);
        __nv_bfloat16 lb = __float2bfloat16(hv - __bfloat162float(hb));
        g_hbhi[(t + 1) & 1][eb * HID + u0 + ej] = hb;
        g_hblo[(t + 1) & 1][eb * HID + u0 + ej] = lb;

        // ---- release: one atomic per CTA onto its group counter ----
        __syncthreads();
        if (tid == 0) {
            __threadfence();
            atomicAdd(&g_cnt[my_grp], 1u);
        }

        out[(size_t)t * (BATCH * HID) + eb * HID + u0 + ej] = hv;
    }

    const size_t off = (size_t)T_STEPS * BATCH * HID;
    out[off + eb * HID + u0 + ej]               = h_last;
    out[off + BATCH * HID + eb * HID + u0 + ej] = c_reg;
}

extern "C" void kernel_launch(void* const* d_in, const int* in_sizes, int n_in,
                              void* d_out, int out_size) {
    const float* X  = (const float*)d_in[0];
    const float* Wf = (const float*)d_in[1];
    const float* bf = (const float*)d_in[2];
    const float* Wi = (const float*)d_in[3];
    const float* bi = (const float*)d_in[4];
    const float* Wg = (const float*)d_in[5];
    const float* bg = (const float*)d_in[6];
    const float* Wo = (const float*)d_in[7];
    const float* bo = (const float*)d_in[8];
    float* out = (float*)d_out;

    cudaFuncSetAttribute(xgemm_mma_kernel,
                         cudaFuncAttributeMaxDynamicSharedMemorySize, SM_MMA_TOTAL);
    cudaFuncSetAttribute(lstm_rec_mma_kernel,
                         cudaFuncAttributeMaxDynamicSharedMemorySize, SM_REC_TOTAL);

    init_kernel<<<64, 256>>>();
    split_kernel<<<1024, 256>>>(X, Wf, bf, Wi, bi, Wg, bg, Wo, bo);
    xgemm_mma_kernel<<<dim3(16, 256), 256, SM_MMA_TOTAL>>>();
    lstm_rec_mma_kernel<<<128, 256, SM_REC_TOTAL>>>(Wf, Wi, Wg, Wo, out);
}